// round 17
// baseline (speedup 1.0000x reference)
#include <cuda_runtime.h>
#include <cuda_bf16.h>
#include <cstdint>

#define BQ   64
#define SEQ  341
#define DIM  768
#define NH   12
#define HD   64
#define MROWS (BQ * SEQ)      // 21824
#define QKV_COLS (3 * DIM)    // 2304
#define ROWTILES 171          // ceil(21824/128)
#define KTILES   24           // 768/32
#define PADROWS  64           // zero padding rows for OOB tile reads
#define VTSTRIDE 384          // g_vt key-dim row stride (>= 6*64, mult of 4)

// Scratch (no device allocation allowed). __device__ globals are zero-init;
// padding regions are never written so they stay zero across graph replays.
// g_q/g_k: tf32 bits, d-dim PERMUTED within 32-groups: perm(c)=(c&3)*8+(c>>2).
// g_vt: tf32 bits, transposed [bh][d][key], key-dim permuted within 32-groups.
__device__ uint32_t g_q[((size_t)BQ * NH * SEQ + PADROWS) * HD];
__device__ uint32_t g_k[((size_t)BQ * NH * SEQ + PADROWS) * HD];
__device__ uint32_t g_vt[(size_t)BQ * NH * HD * VTSTRIDE];

// Pre-formatted tf32-bit tiled buffers: [tile][kTile][r=128][permuted c=32]
__device__ uint32_t g_xt[(size_t)ROWTILES * KTILES * 4096];
__device__ uint32_t g_aot[(size_t)ROWTILES * KTILES * 4096];
__device__ uint32_t g_wq[(size_t)(QKV_COLS / 128) * KTILES * 4096];
__device__ uint32_t g_wp[(size_t)(DIM / 128) * KTILES * 4096];

// ---------------------------------------------------------------------------
// Helpers
// ---------------------------------------------------------------------------

__device__ __forceinline__ uint32_t to_tf32(float x) {
    uint32_t y;
    asm("cvt.rna.tf32.f32 %0, %1;" : "=r"(y) : "f"(x));
    return y;
}

__device__ __forceinline__ void mma_tf32(float& c0, float& c1, float& c2, float& c3,
                                         uint32_t a0, uint32_t a1, uint32_t a2, uint32_t a3,
                                         uint32_t b0, uint32_t b1) {
    asm volatile(
        "mma.sync.aligned.m16n8k8.row.col.f32.tf32.tf32.f32 "
        "{%0,%1,%2,%3}, {%4,%5,%6,%7}, {%8,%9}, {%0,%1,%2,%3};\n"
        : "+f"(c0), "+f"(c1), "+f"(c2), "+f"(c3)
        : "r"(a0), "r"(a1), "r"(a2), "r"(a3), "r"(b0), "r"(b1));
}

#define CP_ASYNC16(dst32, src) \
    asm volatile("cp.async.cg.shared.global [%0], [%1], 16;\n" :: "r"(dst32), "l"(src))
#define CP_COMMIT()  asm volatile("cp.async.commit_group;\n" ::: "memory")
#define CP_WAIT0()   asm volatile("cp.async.wait_group 0;\n" ::: "memory")

// ---------------------------------------------------------------------------
// Format pass: fp32 row-major [nrows x 768] -> tiled permuted tf32 bits.
// ---------------------------------------------------------------------------

__global__ __launch_bounds__(192) void fmt_kernel(
    const float* __restrict__ src, uint32_t* __restrict__ dst)
{
    const int m = blockIdx.x;
    const int f = threadIdx.x;          // float4 index 0..191
    const float4 v = *reinterpret_cast<const float4*>(src + (size_t)m * DIM + f * 4);
    const int rowTile = m >> 7;
    const int r = m & 127;
    const int kt = f >> 3;
    const int f4 = f & 7;
    uint32_t* p = dst + ((size_t)(rowTile * KTILES + kt) * 128 + r) * 32 + f4;
    p[0]  = to_tf32(v.x);
    p[8]  = to_tf32(v.y);
    p[16] = to_tf32(v.z);
    p[24] = to_tf32(v.w);
}

// ---------------------------------------------------------------------------
// TF32 GEMM on pre-formatted tiles (R16 version — validated, untouched).
// ---------------------------------------------------------------------------

__global__ __launch_bounds__(256) void gemm_fmt_kernel(
    const uint32_t* __restrict__ At, const uint32_t* __restrict__ Wt,
    const float* __restrict__ bias, float* __restrict__ out, int mode)
{
    extern __shared__ uint32_t sh[];
    uint32_t* sA = sh;           // [2][4096]
    uint32_t* sB = sh + 8192;    // [2][4096]

    const int tid  = threadIdx.x;
    const int warp = tid >> 5;
    const int lane = tid & 31;
    const int warp_m = warp >> 1;
    const int warp_n = warp & 1;
    const int grp  = lane >> 2;
    const int thr  = lane & 3;
    const int colT = blockIdx.x;
    const int rowT = blockIdx.y;

    const uint32_t* gA = At + (size_t)rowT * KTILES * 4096;
    const uint32_t* gB = Wt + (size_t)colT * KTILES * 4096;

    float acc[2][8][4];
    #pragma unroll
    for (int i = 0; i < 2; i++)
        #pragma unroll
        for (int j = 0; j < 8; j++)
            #pragma unroll
            for (int c = 0; c < 4; c++) acc[i][j][c] = 0.f;

    #define SWZ(off) (((off) & ~31) | (((off) & 31) ^ ((((off) >> 5) & 1) << 2)))

    {
        uint32_t dA = (uint32_t)__cvta_generic_to_shared(sA);
        uint32_t dB = (uint32_t)__cvta_generic_to_shared(sB);
        #pragma unroll
        for (int i = 0; i < 4; i++) {
            int off = (i * 256 + tid) * 4;
            int sw  = SWZ(off);
            CP_ASYNC16(dA + sw * 4, gA + off);
            CP_ASYNC16(dB + sw * 4, gB + off);
        }
        CP_COMMIT();
    }

    const int sw4 = (grp & 1) << 2;

    for (int kt = 0; kt < KTILES; kt++) {
        const int cur = kt & 1;
        CP_WAIT0();
        __syncthreads();

        if (kt + 1 < KTILES) {
            const int nxt = cur ^ 1;
            uint32_t dA = (uint32_t)__cvta_generic_to_shared(sA + nxt * 4096);
            uint32_t dB = (uint32_t)__cvta_generic_to_shared(sB + nxt * 4096);
            const uint32_t* srcA = gA + (size_t)(kt + 1) * 4096;
            const uint32_t* srcB = gB + (size_t)(kt + 1) * 4096;
            #pragma unroll
            for (int i = 0; i < 4; i++) {
                int off = (i * 256 + tid) * 4;
                int sw  = SWZ(off);
                CP_ASYNC16(dA + sw * 4, srcA + off);
                CP_ASYNC16(dB + sw * 4, srcB + off);
            }
            CP_COMMIT();
        }

        const uint32_t* A0 = sA + cur * 4096;
        const uint32_t* B0 = sB + cur * 4096;

        #pragma unroll
        for (int half = 0; half < 2; half++) {
            const int fc = (thr * 8 + half * 4) ^ sw4;
            uint4 va[2][2];
            #pragma unroll
            for (int ms = 0; ms < 2; ms++) {
                int r0 = warp_m * 32 + ms * 16 + grp;
                va[ms][0] = *reinterpret_cast<const uint4*>(&A0[r0 * 32 + fc]);
                va[ms][1] = *reinterpret_cast<const uint4*>(&A0[(r0 + 8) * 32 + fc]);
            }
            #pragma unroll
            for (int ns = 0; ns < 8; ns++) {
                int rn = warp_n * 64 + ns * 8 + grp;
                uint4 vb = *reinterpret_cast<const uint4*>(&B0[rn * 32 + fc]);
                #pragma unroll
                for (int ms = 0; ms < 2; ms++) {
                    mma_tf32(acc[ms][ns][0], acc[ms][ns][1], acc[ms][ns][2], acc[ms][ns][3],
                             va[ms][0].x, va[ms][1].x, va[ms][0].y, va[ms][1].y,
                             vb.x, vb.y);
                    mma_tf32(acc[ms][ns][0], acc[ms][ns][1], acc[ms][ns][2], acc[ms][ns][3],
                             va[ms][0].z, va[ms][1].z, va[ms][0].w, va[ms][1].w,
                             vb.z, vb.w);
                }
            }
        }
        __syncthreads();
    }

    // Epilogue. mode 0 writes q/k permuted-in-d and v transposed+key-permuted.
    #pragma unroll
    for (int ms = 0; ms < 2; ms++) {
        #pragma unroll
        for (int ns = 0; ns < 8; ns++) {
            #pragma unroll
            for (int c = 0; c < 4; c++) {
                int m = rowT * 128 + warp_m * 32 + ms * 16 + grp + ((c >= 2) ? 8 : 0);
                if (m >= MROWS) continue;
                int e = colT * 128 + warp_n * 64 + ns * 8 + thr * 2 + (c & 1);
                float val = acc[ms][ns][c] + __ldg(&bias[e]);
                if (mode == 0) {
                    int b = m / SEQ;
                    int n = m - b * SEQ;
                    int which = e / DIM;
                    int d = e - which * DIM;
                    int h = d >> 6;
                    int hh = d & 63;
                    int bh = b * NH + h;
                    if (which == 2) {
                        // v -> g_vt[bh][hh][perm(key n)]
                        int np = (n & ~31) + ((n & 3) * 8) + ((n & 31) >> 2);
                        g_vt[((size_t)bh * HD + hh) * VTSTRIDE + np] = to_tf32(val);
                    } else {
                        // q/k -> permuted d within 32-groups
                        int hp = (hh & 32) + ((hh & 3) * 8) + ((hh & 31) >> 2);
                        uint32_t* dst = (which == 0) ? g_q : g_k;
                        dst[((size_t)bh * SEQ + n) * HD + hp] = to_tf32(val);
                    }
                } else {
                    out[(size_t)m * DIM + e] = val;
                }
            }
        }
    }
    #undef SWZ
}

// ---------------------------------------------------------------------------
// Tensor-core flash attention, K-tile 64, cp.async staging, uint4 fragment
// loads from permuted layouts. 104 KB smem -> 2 CTAs/SM.
// ---------------------------------------------------------------------------

#define AS 68    // row stride (64 + 4); 68 % 32 == 4 phase-splits grp parities
#define KT 64    // key tile
#define NEGINF (-1e30f)

__device__ __forceinline__ int kmax_for_row(int r) {
    if (r == 0)  return SEQ;   // CLS attends everywhere
    if (r < 5)   return 5;
    if (r < 21)  return 21;
    if (r < 85)  return 85;
    return SEQ;
}

__global__ __launch_bounds__(256) void attn_mma_kernel() {
    extern __shared__ uint32_t sm[];
    uint32_t* Qs  = sm;                 // [128][AS] (d permuted)
    uint32_t* Ks  = Qs + 128 * AS;      // [64][AS]  (d permuted)
    uint32_t* Vts = Ks + KT * AS;       // [64 d][AS] (key permuted)
    uint32_t* Ps  = Vts + KT * AS;      // [128][AS] (key permuted)

    const int tid  = threadIdx.x;
    const int warp = tid >> 5;
    const int lane = tid & 31;
    const int grp  = lane >> 2;
    const int thr  = lane & 3;
    const int bh   = blockIdx.x;
    const int qt   = blockIdx.y;
    const size_t base = (size_t)bh * SEQ * HD;
    const size_t vtbase = (size_t)bh * HD * VTSTRIDE;
    const int b = bh / NH;
    const int h = bh - b * NH;
    const int w16 = warp * 16;

    const uint32_t qsA = (uint32_t)__cvta_generic_to_shared(Qs);
    const uint32_t ksA = (uint32_t)__cvta_generic_to_shared(Ks);
    const uint32_t vsA = (uint32_t)__cvta_generic_to_shared(Vts);

    // Stage Q tile [128 x 64] via cp.async (permuted tf32 bits)
    #pragma unroll
    for (int i = 0; i < 8; i++) {
        int idx = i * 256 + tid;        // 0..2047
        int r   = idx >> 4;             // 0..127
        int c4  = (idx & 15) * 4;
        CP_ASYNC16(qsA + (r * AS + c4) * 4,
                   g_q + base + (size_t)(qt * 128 + r) * HD + c4);
    }
    CP_COMMIT();

    const int gr0 = qt * 128 + w16 + grp;
    const int gr1 = gr0 + 8;
    const int km0 = kmax_for_row(gr0);
    const int km1 = kmax_for_row(gr1);
    const int wkm = (qt == 0 && warp == 0) ? SEQ : kmax_for_row(qt * 128 + w16 + 15);

    float m0 = NEGINF, m1 = NEGINF, l0 = 0.f, l1 = 0.f;
    float oacc[8][4];
    #pragma unroll
    for (int no = 0; no < 8; no++)
        #pragma unroll
        for (int c = 0; c < 4; c++) oacc[no][c] = 0.f;

    for (int t = 0; t < 6; t++) {
        __syncthreads();   // prior tile's smem reads done

        // Stage K tile [64 keys x 64 d] and V^T tile [64 d x 64 keys]
        #pragma unroll
        for (int i = 0; i < 4; i++) {
            int idx = i * 256 + tid;    // 0..1023
            int r   = idx >> 4;         // 0..63
            int c4  = (idx & 15) * 4;
            CP_ASYNC16(ksA + (r * AS + c4) * 4,
                       g_k + base + (size_t)(t * KT + r) * HD + c4);
            CP_ASYNC16(vsA + (r * AS + c4) * 4,
                       g_vt + vtbase + (size_t)r * VTSTRIDE + t * KT + c4);
        }
        CP_COMMIT();
        CP_WAIT0();        // Q (t=0) + this tile's K/Vt complete
        __syncthreads();

        if (t * KT >= wkm) continue;

        // S = Q K^T : 16 q-rows x 64 keys (uint4 fragment loads)
        float sacc[8][4];
        #pragma unroll
        for (int ns = 0; ns < 8; ns++)
            #pragma unroll
            for (int c = 0; c < 4; c++) sacc[ns][c] = 0.f;

        #pragma unroll
        for (int g = 0; g < 2; g++) {
            const int fb = g * 32 + thr * 8;
            uint4 qa0 = *reinterpret_cast<const uint4*>(&Qs[(w16 + grp)     * AS + fb]);
            uint4 qa1 = *reinterpret_cast<const uint4*>(&Qs[(w16 + grp)     * AS + fb + 4]);
            uint4 qb0 = *reinterpret_cast<const uint4*>(&Qs[(w16 + grp + 8) * AS + fb]);
            uint4 qb1 = *reinterpret_cast<const uint4*>(&Qs[(w16 + grp + 8) * AS + fb + 4]);
            #pragma unroll
            for (int ns = 0; ns < 8; ns++) {
                uint4 kb0 = *reinterpret_cast<const uint4*>(&Ks[(ns * 8 + grp) * AS + fb]);
                uint4 kb1 = *reinterpret_cast<const uint4*>(&Ks[(ns * 8 + grp) * AS + fb + 4]);
                mma_tf32(sacc[ns][0], sacc[ns][1], sacc[ns][2], sacc[ns][3],
                         qa0.x, qb0.x, qa0.y, qb0.y, kb0.x, kb0.y);
                mma_tf32(sacc[ns][0], sacc[ns][1], sacc[ns][2], sacc[ns][3],
                         qa0.z, qb0.z, qa0.w, qb0.w, kb0.z, kb0.w);
                mma_tf32(sacc[ns][0], sacc[ns][1], sacc[ns][2], sacc[ns][3],
                         qa1.x, qb1.x, qa1.y, qb1.y, kb1.x, kb1.y);
                mma_tf32(sacc[ns][0], sacc[ns][1], sacc[ns][2], sacc[ns][3],
                         qa1.z, qb1.z, qa1.w, qb1.w, kb1.z, kb1.w);
            }
        }

        // Scale + prefix mask + tile max (D-layout mapping unchanged)
        float tmax0 = NEGINF, tmax1 = NEGINF;
        #pragma unroll
        for (int ns = 0; ns < 8; ns++) {
            int j0 = t * KT + ns * 8 + thr * 2;
            sacc[ns][0] = (j0     < km0) ? sacc[ns][0] * 0.125f : NEGINF;
            sacc[ns][1] = (j0 + 1 < km0) ? sacc[ns][1] * 0.125f : NEGINF;
            sacc[ns][2] = (j0     < km1) ? sacc[ns][2] * 0.125f : NEGINF;
            sacc[ns][3] = (j0 + 1 < km1) ? sacc[ns][3] * 0.125f : NEGINF;
            tmax0 = fmaxf(tmax0, fmaxf(sacc[ns][0], sacc[ns][1]));
            tmax1 = fmaxf(tmax1, fmaxf(sacc[ns][2], sacc[ns][3]));
        }
        tmax0 = fmaxf(tmax0, __shfl_xor_sync(0xFFFFFFFFu, tmax0, 1));
        tmax0 = fmaxf(tmax0, __shfl_xor_sync(0xFFFFFFFFu, tmax0, 2));
        tmax1 = fmaxf(tmax1, __shfl_xor_sync(0xFFFFFFFFu, tmax1, 1));
        tmax1 = fmaxf(tmax1, __shfl_xor_sync(0xFFFFFFFFu, tmax1, 2));

        float mn0 = fmaxf(m0, tmax0);
        float mn1 = fmaxf(m1, tmax1);
        float cr0 = __expf(m0 - mn0);
        float cr1 = __expf(m1 - mn1);
        m0 = mn0; m1 = mn1;

        float rs0 = 0.f, rs1 = 0.f;
        #pragma unroll
        for (int ns = 0; ns < 8; ns++) {
            sacc[ns][0] = __expf(sacc[ns][0] - mn0);
            sacc[ns][1] = __expf(sacc[ns][1] - mn0);
            sacc[ns][2] = __expf(sacc[ns][2] - mn1);
            sacc[ns][3] = __expf(sacc[ns][3] - mn1);
            rs0 += sacc[ns][0] + sacc[ns][1];
            rs1 += sacc[ns][2] + sacc[ns][3];
        }
        rs0 += __shfl_xor_sync(0xFFFFFFFFu, rs0, 1);
        rs0 += __shfl_xor_sync(0xFFFFFFFFu, rs0, 2);
        rs1 += __shfl_xor_sync(0xFFFFFFFFu, rs1, 1);
        rs1 += __shfl_xor_sync(0xFFFFFFFFu, rs1, 2);
        l0 = l0 * cr0 + rs0;
        l1 = l1 * cr1 + rs1;

        #pragma unroll
        for (int no = 0; no < 8; no++) {
            oacc[no][0] *= cr0; oacc[no][1] *= cr0;
            oacc[no][2] *= cr1; oacc[no][3] *= cr1;
        }

        // P tile written at key-permuted positions (read back as uint4 A-frags)
        #pragma unroll
        for (int ns = 0; ns < 8; ns++) {
            int col = ns * 8 + thr * 2;           // even
            int pp  = (col & 32) + ((col & 3) * 8) + ((col & 31) >> 2);
            // col, col+1 -> pp, pp+8  (since (col+1)&3 = (col&3)+1)
            Ps[(w16 + grp)     * AS + pp]     = to_tf32(sacc[ns][0]);
            Ps[(w16 + grp)     * AS + pp + 8] = to_tf32(sacc[ns][1]);
            Ps[(w16 + grp + 8) * AS + pp]     = to_tf32(sacc[ns][2]);
            Ps[(w16 + grp + 8) * AS + pp + 8] = to_tf32(sacc[ns][3]);
        }
        __syncwarp();

        // O += P V : A from Ps (key-permuted), B from Vts (key-permuted)
        #pragma unroll
        for (int g = 0; g < 2; g++) {
            const int fb = g * 32 + thr * 8;
            uint4 pa0 = *reinterpret_cast<const uint4*>(&Ps[(w16 + grp)     * AS + fb]);
            uint4 pa1 = *reinterpret_cast<const uint4*>(&Ps[(w16 + grp)     * AS + fb + 4]);
            uint4 pb0 = *reinterpret_cast<const uint4*>(&Ps[(w16 + grp + 8) * AS + fb]);
            uint4 pb1 = *reinterpret_cast<const uint4*>(&Ps[(w16 + grp + 8) * AS + fb + 4]);
            #pragma unroll
            for (int no = 0; no < 8; no++) {
                uint4 vb0 = *reinterpret_cast<const uint4*>(&Vts[(no * 8 + grp) * AS + fb]);
                uint4 vb1 = *reinterpret_cast<const uint4*>(&Vts[(no * 8 + grp) * AS + fb + 4]);
                mma_tf32(oacc[no][0], oacc[no][1], oacc[no][2], oacc[no][3],
                         pa0.x, pb0.x, pa0.y, pb0.y, vb0.x, vb0.y);
                mma_tf32(oacc[no][0], oacc[no][1], oacc[no][2], oacc[no][3],
                         pa0.z, pb0.z, pa0.w, pb0.w, vb0.z, vb0.w);
                mma_tf32(oacc[no][0], oacc[no][1], oacc[no][2], oacc[no][3],
                         pa1.x, pb1.x, pa1.y, pb1.y, vb1.x, vb1.y);
                mma_tf32(oacc[no][0], oacc[no][1], oacc[no][2], oacc[no][3],
                         pa1.z, pb1.z, pa1.w, pb1.w, vb1.z, vb1.w);
            }
        }
    }

    // Normalize, write directly into tiled tf32 buffer g_aot.
    float inv0 = 1.f / l0;
    float inv1 = 1.f / l1;
    #pragma unroll
    for (int no = 0; no < 8; no++) {
        int d = no * 8 + thr * 2;
        int e = h * HD + d;
        int ktile = e >> 5;
        int c = e & 31;
        uint32_t coff = (uint32_t)((c & 3) * 8 + (c >> 2));
        if (gr0 < SEQ) {
            int mg = b * SEQ + gr0;
            uint32_t* p = g_aot + ((size_t)((mg >> 7) * KTILES + ktile) * 128 + (mg & 127)) * 32 + coff;
            p[0] = to_tf32(oacc[no][0] * inv0);
            p[8] = to_tf32(oacc[no][1] * inv0);
        }
        if (gr1 < SEQ) {
            int mg = b * SEQ + gr1;
            uint32_t* p = g_aot + ((size_t)((mg >> 7) * KTILES + ktile) * 128 + (mg & 127)) * 32 + coff;
            p[0] = to_tf32(oacc[no][2] * inv1);
            p[8] = to_tf32(oacc[no][3] * inv1);
        }
    }
}

// ---------------------------------------------------------------------------

extern "C" void kernel_launch(void* const* d_in, const int* in_sizes, int n_in,
                              void* d_out, int out_size) {
    const float* x      = (const float*)d_in[0];
    const float* qkv_w  = (const float*)d_in[1];
    const float* qkv_b  = (const float*)d_in[2];
    const float* proj_w = (const float*)d_in[3];
    const float* proj_b = (const float*)d_in[4];
    float* out = (float*)d_out;

    uint32_t* xt;  cudaGetSymbolAddress((void**)&xt,  g_xt);
    uint32_t* aot; cudaGetSymbolAddress((void**)&aot, g_aot);
    uint32_t* wq;  cudaGetSymbolAddress((void**)&wq,  g_wq);
    uint32_t* wp;  cudaGetSymbolAddress((void**)&wp,  g_wp);

    const int smem_gemm = 2 * 2 * 4096 * (int)sizeof(uint32_t);  // 65536
    const int smem_attn = (128 * AS + KT * AS + KT * AS + 128 * AS) * (int)sizeof(uint32_t);
    cudaFuncSetAttribute(gemm_fmt_kernel, cudaFuncAttributeMaxDynamicSharedMemorySize, smem_gemm);
    cudaFuncSetAttribute(attn_mma_kernel, cudaFuncAttributeMaxDynamicSharedMemorySize, smem_attn);

    // Format passes
    fmt_kernel<<<MROWS, 192>>>(x, xt);
    fmt_kernel<<<QKV_COLS, 192>>>(qkv_w, wq);
    fmt_kernel<<<DIM, 192>>>(proj_w, wp);

    // QKV GEMM
    dim3 gQkv(QKV_COLS / 128, ROWTILES);   // 18 x 171
    gemm_fmt_kernel<<<gQkv, 256, smem_gemm>>>(xt, wq, qkv_b, nullptr, 0);

    // Attention (writes g_aot tiled)
    dim3 gAttn(BQ * NH, 3);                // 768 x 3
    attn_mma_kernel<<<gAttn, 256, smem_attn>>>();

    // Proj GEMM
    dim3 gProj(DIM / 128, ROWTILES);       // 6 x 171
    gemm_fmt_kernel<<<gProj, 256, smem_gemm>>>(aot, wp, proj_b, out, 1);
}